// round 7
// baseline (speedup 1.0000x reference)
#include <cuda_runtime.h>
#include <cstdint>
#include <math.h>

#define B_ 64
#define S_ 256
#define H_ 1024
#define G_ 4096
#define NROW (S_*B_)

// ---------------- static scratch ----------------
__device__ float g_x  [NROW*H_];      // embedded, tf32-rounded [S,B,H]
__device__ float g_h1 [NROW*H_];      // layer-1 h seq, rounded [S,B,H]
__device__ float g_xg [(size_t)NROW*G_]; // gate preacts [S,B,4H]
__device__ float g_wxr[2*H_*G_];      // rounded Wx
__device__ float g_whr[2*H_*G_];      // rounded Wh
__device__ float g_hbuf[2][B_*H_];    // rounded h state, double buffered
__device__ float g_cst[B_*H_];        // c state fp32
__device__ float g_hf [B_*H_];        // h state fp32 (unrounded)

// ---------------- helpers ----------------
__device__ __forceinline__ unsigned f2tf(float v) {
    unsigned r; asm("cvt.rna.tf32.f32 %0, %1;" : "=r"(r) : "f"(v)); return r;
}
__device__ __forceinline__ void mma_tf32(float* c, const unsigned* a, const unsigned* b) {
    asm volatile(
        "mma.sync.aligned.m16n8k8.row.col.f32.tf32.tf32.f32 "
        "{%0,%1,%2,%3}, {%4,%5,%6,%7}, {%8,%9}, {%0,%1,%2,%3};"
        : "+f"(c[0]), "+f"(c[1]), "+f"(c[2]), "+f"(c[3])
        : "r"(a[0]), "r"(a[1]), "r"(a[2]), "r"(a[3]), "r"(b[0]), "r"(b[1]));
}
__device__ __forceinline__ void cpa16(void* s, const void* g) {
    unsigned ss = (unsigned)__cvta_generic_to_shared(s);
    asm volatile("cp.async.cg.shared.global [%0], [%1], 16;" :: "r"(ss), "l"(g));
}
__device__ __forceinline__ void cpa_commit() { asm volatile("cp.async.commit_group;"); }
template<int N> __device__ __forceinline__ void cpa_wait() {
    asm volatile("cp.async.wait_group %0;" :: "n"(N));
}
__device__ __forceinline__ float sigm(float x) { return 1.f / (1.f + __expf(-x)); }

// ---------------- embed ----------------
__global__ void embed_kernel(const int* __restrict__ inputs, const float* __restrict__ emb) {
    int rid = blockIdx.x;                  // s*64 + b
    int b = rid & 63, s = rid >> 6;
    int tok = inputs[b * S_ + s];
    float4 v = ((const float4*)(emb + (size_t)tok * H_))[threadIdx.x];
    float4 o;
    o.x = __uint_as_float(f2tf(v.x)); o.y = __uint_as_float(f2tf(v.y));
    o.z = __uint_as_float(f2tf(v.z)); o.w = __uint_as_float(f2tf(v.w));
    ((float4*)(g_x + (size_t)rid * H_))[threadIdx.x] = o;
}

// ---------------- round weights ----------------
__global__ void round_k(const float* __restrict__ src, int which) {
    size_t i = (size_t)blockIdx.x * 256 + threadIdx.x;  // 2,097,152 float4
    float4 v = ((const float4*)src)[i];
    float4 o;
    o.x = __uint_as_float(f2tf(v.x)); o.y = __uint_as_float(f2tf(v.y));
    o.z = __uint_as_float(f2tf(v.z)); o.w = __uint_as_float(f2tf(v.w));
    ((float4*)(which ? g_whr : g_wxr))[i] = o;
}

// ---------------- zero recurrent state ----------------
__global__ void zero_state() {
    int i = blockIdx.x * 256 + threadIdx.x;  // 16384 float4 per buffer
    float4 z = {0.f, 0.f, 0.f, 0.f};
    ((float4*)g_hbuf[0])[i] = z;
    ((float4*)g_cst)[i] = z;
    ((float4*)g_hf)[i] = z;
}

// ---------------- xg GEMM: [16384,1024] @ [1024,4096] + bias ----------------
#define GBM 128
#define GBN 128
#define GBK 32
#define ALD 36
#define BLD 136
#define ABUF (GBM*ALD)
#define BBUF (GBK*BLD)
#define GEMM_SMEM ((2*(ABUF+BBUF))*4)

__global__ void __launch_bounds__(256) gemm_xg(int layer, const float* __restrict__ bias) {
    extern __shared__ float sm[];
    float* As = sm;
    float* Bs = sm + 2 * ABUF;
    const float* A  = layer ? g_h1 : g_x;
    const float* Bw = g_wxr + (size_t)layer * H_ * G_;
    int tid = threadIdx.x;
    int bn = blockIdx.x, bm = blockIdx.y;
    const float* Ab = A + (size_t)bm * GBM * H_;
    const float* Bb = Bw + bn * GBN;
    int wid = tid >> 5, lane = tid & 31, g = lane >> 2, tg = lane & 3;
    int wm = (wid & 1) * 64, wn = (wid >> 1) * 32;

    float acc[4][4][4];
#pragma unroll
    for (int a = 0; a < 4; a++)
#pragma unroll
        for (int b = 0; b < 4; b++)
#pragma unroll
            for (int c = 0; c < 4; c++) acc[a][b][c] = 0.f;

    auto stage = [&](int it) {
        float* Ad = As + (it & 1) * ABUF;
        float* Bd = Bs + (it & 1) * BBUF;
        int k0 = it * GBK;
#pragma unroll
        for (int q = 0; q < 4; q++) {
            int idx = tid + q * 256; int r = idx >> 3, c4 = (idx & 7) << 2;
            cpa16(Ad + r * ALD + c4, Ab + (size_t)r * H_ + k0 + c4);
        }
#pragma unroll
        for (int q = 0; q < 4; q++) {
            int idx = tid + q * 256; int r = idx >> 5, c4 = (idx & 31) << 2;
            cpa16(Bd + r * BLD + c4, Bb + (size_t)(k0 + r) * G_ + c4);
        }
        cpa_commit();
    };

    stage(0);
    for (int it = 0; it < H_ / GBK; it++) {
        if (it + 1 < H_ / GBK) { stage(it + 1); cpa_wait<1>(); }
        else cpa_wait<0>();
        __syncthreads();
        const float* uA = As + (it & 1) * ABUF;
        const float* uB = Bs + (it & 1) * BBUF;
#pragma unroll
        for (int kk = 0; kk < 4; kk++) {
            unsigned af[4][4];
#pragma unroll
            for (int mt = 0; mt < 4; mt++) {
                int r0 = wm + mt * 16 + g; int k = kk * 8 + tg;
                af[mt][0] = __float_as_uint(uA[r0 * ALD + k]);
                af[mt][1] = __float_as_uint(uA[(r0 + 8) * ALD + k]);
                af[mt][2] = __float_as_uint(uA[r0 * ALD + k + 4]);
                af[mt][3] = __float_as_uint(uA[(r0 + 8) * ALD + k + 4]);
            }
            unsigned bf[4][2];
#pragma unroll
            for (int nt = 0; nt < 4; nt++) {
                int n = wn + nt * 8 + g;
                bf[nt][0] = __float_as_uint(uB[(kk * 8 + tg) * BLD + n]);
                bf[nt][1] = __float_as_uint(uB[(kk * 8 + tg + 4) * BLD + n]);
            }
#pragma unroll
            for (int mt = 0; mt < 4; mt++)
#pragma unroll
                for (int nt = 0; nt < 4; nt++) mma_tf32(acc[mt][nt], af[mt], bf[nt]);
        }
        __syncthreads();
    }

#pragma unroll
    for (int mt = 0; mt < 4; mt++)
#pragma unroll
        for (int nt = 0; nt < 4; nt++) {
            int row = bm * GBM + wm + mt * 16 + g;
            int col = bn * GBN + wn + nt * 8 + tg * 2;
            float b0 = bias[col], b1 = bias[col + 1];
            float* o = g_xg + (size_t)row * G_ + col;
            o[0] = acc[mt][nt][0] + b0; o[1] = acc[mt][nt][1] + b1;
            o = g_xg + (size_t)(row + 8) * G_ + col;
            o[0] = acc[mt][nt][2] + b0; o[1] = acc[mt][nt][3] + b1;
        }
}

// ---------------- recurrent step ----------------
// 128 CTAs x 256 thr. CTA owns 8 hidden units (gate cols u0+g in i/f/g/o blocks).
// 8 warps K-split (128 each); h staged in smem quarters; cross-warp smem reduce;
// fused pointwise. smem: stage [2][8][64][36] + rbuf [8][2112].
#define STG_F (2*8*64*36)            // 36864 floats
#define RBF_F (8*2112)               // 16896 floats
#define STEP_SMEM ((STG_F+RBF_F)*4)  // 215040 B

// output layout (floats):
//   x  : [B,S,H]  at 0            (16,777,216)
//   cs : [L,B,H]  at 16,777,216   (stride per layer = B*H = 65,536)
//   hs : [L,B,H]  at 16,908,288
#define OUT_CS 16777216
#define OUT_HS (16777216 + 2 * B_ * H_)
#define LSTRIDE (B_ * H_)

__global__ void __launch_bounds__(256) lstm_step(int layer, int s,
                                                 const int* __restrict__ lengths,
                                                 float* __restrict__ out) {
    extern __shared__ float sm[];
    float* stg  = sm;
    float* rbuf = sm + STG_F;
    const float* whr = g_whr + (size_t)layer * H_ * G_;
    const float* hin = g_hbuf[s & 1];
    float* hout = g_hbuf[(s + 1) & 1];

    int tid = threadIdx.x, w = tid >> 5, lane = tid & 31, g = lane >> 2, tg = lane & 3;
    int u0 = blockIdx.x * 8;
    const float* hsrc = hin + w * 128;

    auto stageq = [&](int q, int buf) {
        float* d = stg + buf * 18432 + w * 2304;
        const float* s4 = hsrc + q * 32;
#pragma unroll
        for (int r = 0; r < 16; r++) {
            int idx = lane + r * 32; int bb = idx >> 3, c4 = (idx & 7) << 2;
            cpa16(d + bb * 36 + c4, s4 + bb * 1024 + c4);
        }
        cpa_commit();
    };

    float acc[2][8][4];
#pragma unroll
    for (int mt = 0; mt < 2; mt++)
#pragma unroll
        for (int nt = 0; nt < 8; nt++)
#pragma unroll
            for (int j = 0; j < 4; j++) acc[mt][nt][j] = 0.f;

    int cI = u0 + g;
    stageq(0, 0);
    for (int q = 0; q < 4; q++) {
        if (q < 3) { stageq(q + 1, (q + 1) & 1); cpa_wait<1>(); }
        else cpa_wait<0>();
        __syncwarp();
        const float* hb = stg + (q & 1) * 18432 + w * 2304;
#pragma unroll
        for (int kc = 0; kc < 4; kc++) {
            int kb = w * 128 + q * 32 + kc * 8;
            const float* w0 = whr + (size_t)(kb + tg) * G_;
            const float* w4 = whr + (size_t)(kb + tg + 4) * G_;
            unsigned a0[4], a1[4];
            a0[0] = __float_as_uint(__ldcg(w0 + cI));
            a0[1] = __float_as_uint(__ldcg(w0 + 1024 + cI));
            a0[2] = __float_as_uint(__ldcg(w4 + cI));
            a0[3] = __float_as_uint(__ldcg(w4 + 1024 + cI));
            a1[0] = __float_as_uint(__ldcg(w0 + 2048 + cI));
            a1[1] = __float_as_uint(__ldcg(w0 + 3072 + cI));
            a1[2] = __float_as_uint(__ldcg(w4 + 2048 + cI));
            a1[3] = __float_as_uint(__ldcg(w4 + 3072 + cI));
#pragma unroll
            for (int nt = 0; nt < 8; nt++) {
                unsigned bb[2];
                bb[0] = __float_as_uint(hb[(nt * 8 + g) * 36 + kc * 8 + tg]);
                bb[1] = __float_as_uint(hb[(nt * 8 + g) * 36 + kc * 8 + tg + 4]);
                mma_tf32(acc[0][nt], a0, bb);
                mma_tf32(acc[1][nt], a1, bb);
            }
        }
    }

    // all-to-all reduce: warp w ends with full sums for its batch tile nt=w
    float* myr = rbuf + w * 2112 + lane * 66;
#pragma unroll
    for (int mt = 0; mt < 2; mt++)
#pragma unroll
        for (int nt = 0; nt < 8; nt++)
#pragma unroll
            for (int j = 0; j < 4; j++) myr[(mt * 8 + nt) * 4 + j] = acc[mt][nt][j];
    __syncthreads();
    float fin[2][4];
#pragma unroll
    for (int mt = 0; mt < 2; mt++)
#pragma unroll
        for (int j = 0; j < 4; j++) fin[mt][j] = 0.f;
#pragma unroll
    for (int src = 0; src < 8; src++) {
        const float* rr = rbuf + src * 2112 + lane * 66;
#pragma unroll
        for (int mt = 0; mt < 2; mt++)
#pragma unroll
            for (int j = 0; j < 4; j++) fin[mt][j] += rr[(mt * 8 + w) * 4 + j];
    }

    // pointwise: lane holds gates for unit u0+g, batches w*8+tg*2+{0,1}
    int u = u0 + g;
#pragma unroll
    for (int hh = 0; hh < 2; hh++) {
        int bb = w * 8 + tg * 2 + hh;
        const float* xga = g_xg + (size_t)(s * 64 + bb) * G_;
        float iv = fin[0][hh]     + xga[u];
        float fv = fin[0][2 + hh] + xga[1024 + u];
        float gv = fin[1][hh]     + xga[2048 + u];
        float ov = fin[1][2 + hh] + xga[3072 + u];
        float co = g_cst[bb * 1024 + u];
        float ho = g_hf[bb * 1024 + u];
        float cn = sigm(fv) * co + sigm(iv) * tanhf(gv);
        float hn = sigm(ov) * tanhf(cn);
        bool m = s < lengths[bb];
        float c  = m ? cn : co;
        float hf = m ? hn : ho;
        g_cst[bb * 1024 + u] = c;
        g_hf[bb * 1024 + u] = hf;
        float hr = __uint_as_float(f2tf(hf));
        hout[bb * 1024 + u] = hr;
        if (layer == 0) g_h1[((size_t)s * 64 + bb) * 1024 + u] = hr;
        else            out[((size_t)bb * 256 + s) * 1024 + u] = hf;
        if (s == S_ - 1) {
            out[OUT_CS + layer * LSTRIDE + bb * 1024 + u] = c;   // cs[layer]
            out[OUT_HS + layer * LSTRIDE + bb * 1024 + u] = hf;  // hs[layer]
        }
    }
}

// ---------------- launch ----------------
extern "C" void kernel_launch(void* const* d_in, const int* in_sizes, int n_in,
                              void* d_out, int out_size) {
    const int*   inputs  = (const int*)d_in[0];
    const int*   lengths = (const int*)d_in[1];
    const float* emb     = (const float*)d_in[3];
    const float* Wx      = (const float*)d_in[4];
    const float* Wh      = (const float*)d_in[5];
    const float* bias    = (const float*)d_in[6];
    float* out = (float*)d_out;

    cudaFuncSetAttribute(gemm_xg,   cudaFuncAttributeMaxDynamicSharedMemorySize, GEMM_SMEM);
    cudaFuncSetAttribute(lstm_step, cudaFuncAttributeMaxDynamicSharedMemorySize, STEP_SMEM);

    round_k<<<8192, 256>>>(Wx, 0);
    round_k<<<8192, 256>>>(Wh, 1);
    embed_kernel<<<NROW, 256>>>(inputs, emb);

    for (int l = 0; l < 2; l++) {
        zero_state<<<64, 256>>>();
        gemm_xg<<<dim3(32, 128), 256, GEMM_SMEM>>>(l, bias + l * G_);
        for (int s = 0; s < S_; s++)
            lstm_step<<<128, 256, STEP_SMEM>>>(l, s, lengths, out);
    }
}

// round 9
// speedup vs baseline: 1.8043x; 1.8043x over previous
#include <cuda_runtime.h>
#include <cstdint>
#include <math.h>

#define B_ 64
#define S_ 256
#define H_ 1024
#define G_ 4096
#define NROW (S_*B_)
#define NCTA 128

// ---------------- static scratch ----------------
__device__ float g_x  [NROW*H_];         // embedded, tf32-rounded [S,B,H]
__device__ float g_h1 [NROW*H_];         // layer-1 h seq, rounded [S,B,H]
__device__ float g_xg [(size_t)NROW*G_]; // gate preacts [S,B,4H]
__device__ float g_wxr[2*H_*G_];         // rounded Wx
__device__ float g_whr[2*H_*G_];         // rounded Wh
__device__ float g_hbuf[2][B_*H_];       // rounded h state, double buffered
__device__ unsigned g_bar_count = 0;
__device__ unsigned g_bar_gen   = 0;

// ---------------- helpers ----------------
__device__ __forceinline__ unsigned f2tf(float v) {
    unsigned r; asm("cvt.rna.tf32.f32 %0, %1;" : "=r"(r) : "f"(v)); return r;
}
__device__ __forceinline__ void mma_tf32(float* c, const unsigned* a, const unsigned* b) {
    asm volatile(
        "mma.sync.aligned.m16n8k8.row.col.f32.tf32.tf32.f32 "
        "{%0,%1,%2,%3}, {%4,%5,%6,%7}, {%8,%9}, {%0,%1,%2,%3};"
        : "+f"(c[0]), "+f"(c[1]), "+f"(c[2]), "+f"(c[3])
        : "r"(a[0]), "r"(a[1]), "r"(a[2]), "r"(a[3]), "r"(b[0]), "r"(b[1]));
}
__device__ __forceinline__ void cpa16(void* s, const void* g) {
    unsigned ss = (unsigned)__cvta_generic_to_shared(s);
    asm volatile("cp.async.cg.shared.global [%0], [%1], 16;" :: "r"(ss), "l"(g));
}
__device__ __forceinline__ void cpa_commit() { asm volatile("cp.async.commit_group;"); }
template<int N> __device__ __forceinline__ void cpa_wait() {
    asm volatile("cp.async.wait_group %0;" :: "n"(N));
}
__device__ __forceinline__ float sigm(float x) { return 1.f / (1.f + __expf(-x)); }

__device__ __forceinline__ void grid_bar() {
    __syncthreads();
    if (threadIdx.x == 0) {
        __threadfence();
        volatile unsigned* genp = &g_bar_gen;
        unsigned old = *genp;
        unsigned prev = atomicInc(&g_bar_count, NCTA - 1);
        if (prev == NCTA - 1) {
            __threadfence();
            *genp = old + 1;
        } else {
            while (*genp == old) __nanosleep(64);
        }
        __threadfence();
    }
    __syncthreads();
}

// ---------------- embed ----------------
__global__ void embed_kernel(const int* __restrict__ inputs, const float* __restrict__ emb) {
    int rid = blockIdx.x;                  // s*64 + b
    int b = rid & 63, s = rid >> 6;
    int tok = inputs[b * S_ + s];
    float4 v = ((const float4*)(emb + (size_t)tok * H_))[threadIdx.x];
    float4 o;
    o.x = __uint_as_float(f2tf(v.x)); o.y = __uint_as_float(f2tf(v.y));
    o.z = __uint_as_float(f2tf(v.z)); o.w = __uint_as_float(f2tf(v.w));
    ((float4*)(g_x + (size_t)rid * H_))[threadIdx.x] = o;
}

// ---------------- round weights ----------------
__global__ void round_k(const float* __restrict__ src, int which) {
    size_t i = (size_t)blockIdx.x * 256 + threadIdx.x;  // 2,097,152 float4
    float4 v = ((const float4*)src)[i];
    float4 o;
    o.x = __uint_as_float(f2tf(v.x)); o.y = __uint_as_float(f2tf(v.y));
    o.z = __uint_as_float(f2tf(v.z)); o.w = __uint_as_float(f2tf(v.w));
    ((float4*)(which ? g_whr : g_wxr))[i] = o;
}

// ---------------- xg GEMM: [16384,1024] @ [1024,4096] + bias ----------------
#define GBM 128
#define GBN 128
#define GBK 32
#define ALD 36
#define BLD 136
#define ABUF (GBM*ALD)
#define BBUF (GBK*BLD)
#define GEMM_SMEM ((2*(ABUF+BBUF))*4)

__global__ void __launch_bounds__(256) gemm_xg(int layer, const float* __restrict__ bias) {
    extern __shared__ float sm[];
    float* As = sm;
    float* Bs = sm + 2 * ABUF;
    const float* A  = layer ? g_h1 : g_x;
    const float* Bw = g_wxr + (size_t)layer * H_ * G_;
    int tid = threadIdx.x;
    int bn = blockIdx.x, bm = blockIdx.y;
    const float* Ab = A + (size_t)bm * GBM * H_;
    const float* Bb = Bw + bn * GBN;
    int wid = tid >> 5, lane = tid & 31, g = lane >> 2, tg = lane & 3;
    int wm = (wid & 1) * 64, wn = (wid >> 1) * 32;

    float acc[4][4][4];
#pragma unroll
    for (int a = 0; a < 4; a++)
#pragma unroll
        for (int b = 0; b < 4; b++)
#pragma unroll
            for (int c = 0; c < 4; c++) acc[a][b][c] = 0.f;

    auto stage = [&](int it) {
        float* Ad = As + (it & 1) * ABUF;
        float* Bd = Bs + (it & 1) * BBUF;
        int k0 = it * GBK;
#pragma unroll
        for (int q = 0; q < 4; q++) {
            int idx = tid + q * 256; int r = idx >> 3, c4 = (idx & 7) << 2;
            cpa16(Ad + r * ALD + c4, Ab + (size_t)r * H_ + k0 + c4);
        }
#pragma unroll
        for (int q = 0; q < 4; q++) {
            int idx = tid + q * 256; int r = idx >> 5, c4 = (idx & 31) << 2;
            cpa16(Bd + r * BLD + c4, Bb + (size_t)(k0 + r) * G_ + c4);
        }
        cpa_commit();
    };

    stage(0);
    for (int it = 0; it < H_ / GBK; it++) {
        if (it + 1 < H_ / GBK) { stage(it + 1); cpa_wait<1>(); }
        else cpa_wait<0>();
        __syncthreads();
        const float* uA = As + (it & 1) * ABUF;
        const float* uB = Bs + (it & 1) * BBUF;
#pragma unroll
        for (int kk = 0; kk < 4; kk++) {
            unsigned af[4][4];
#pragma unroll
            for (int mt = 0; mt < 4; mt++) {
                int r0 = wm + mt * 16 + g; int k = kk * 8 + tg;
                af[mt][0] = __float_as_uint(uA[r0 * ALD + k]);
                af[mt][1] = __float_as_uint(uA[(r0 + 8) * ALD + k]);
                af[mt][2] = __float_as_uint(uA[r0 * ALD + k + 4]);
                af[mt][3] = __float_as_uint(uA[(r0 + 8) * ALD + k + 4]);
            }
            unsigned bf[4][2];
#pragma unroll
            for (int nt = 0; nt < 4; nt++) {
                int n = wn + nt * 8 + g;
                bf[nt][0] = __float_as_uint(uB[(kk * 8 + tg) * BLD + n]);
                bf[nt][1] = __float_as_uint(uB[(kk * 8 + tg + 4) * BLD + n]);
            }
#pragma unroll
            for (int mt = 0; mt < 4; mt++)
#pragma unroll
                for (int nt = 0; nt < 4; nt++) mma_tf32(acc[mt][nt], af[mt], bf[nt]);
        }
        __syncthreads();
    }

#pragma unroll
    for (int mt = 0; mt < 4; mt++)
#pragma unroll
        for (int nt = 0; nt < 4; nt++) {
            int row = bm * GBM + wm + mt * 16 + g;
            int col = bn * GBN + wn + nt * 8 + tg * 2;
            float b0 = bias[col], b1 = bias[col + 1];
            float* o = g_xg + (size_t)row * G_ + col;
            o[0] = acc[mt][nt][0] + b0; o[1] = acc[mt][nt][1] + b1;
            o = g_xg + (size_t)(row + 8) * G_ + col;
            o[0] = acc[mt][nt][2] + b0; o[1] = acc[mt][nt][3] + b1;
        }
}

// ---------------- persistent recurrent kernel ----------------
// 128 CTAs x 256 thr, 1 CTA/SM, all 256 steps in one launch.
// smem (floats): sWh[1024][32] swizzled @0 (32768), hstage 2x[8][64][20] @32768
// (20480), sXg 2x2048 @53248 (4096). rbuf aliases hstage. Total 57344 f = 229376 B.
#define SWH_F 32768
#define STGB_F 10240
#define SXG_F 53248
#define PS_SMEM (57344*4)

// output layout (floats):
#define OUT_CS 16777216
#define OUT_HS (16777216 + 2 * B_ * H_)
#define LSTRIDE (B_ * H_)

__global__ void __launch_bounds__(256) lstm_pers(int layer,
                                                 const int* __restrict__ lengths,
                                                 float* __restrict__ out) {
    extern __shared__ float sm[];
    float* sWh  = sm;
    float* sStg = sm + SWH_F;
    float* sXg  = sm + SXG_F;
    float* rbuf = sm + SWH_F;     // alias: used only after extra __syncthreads

    const float* whL = g_whr + (size_t)layer * H_ * G_;
    int tid = threadIdx.x, w = tid >> 5, lane = tid & 31, g = lane >> 2, tg = lane & 3;
    int u0 = blockIdx.x * 8;

    // ---- one-time: load CTA's Wh slice into swizzled smem ----
    for (int idx = tid; idx < 32768; idx += 256) {
        int k = idx >> 5, c = idx & 31;
        int gate = c >> 3, gg = c & 7;
        int cs = (((gate ^ (k & 3)) << 3) | gg);
        sWh[(k << 5) + cs] = whL[(size_t)k * G_ + (gate << 10) + u0 + gg];
    }

    float creg[2] = {0.f, 0.f}, hreg[2] = {0.f, 0.f};
    int lenr[2];
#pragma unroll
    for (int hh = 0; hh < 2; hh++) lenr[hh] = lengths[w * 8 + tg * 2 + hh];

    auto prefetch_xg = [&](int s) {
        const float* xgS = g_xg + (size_t)s * 64 * G_;
        float* dst = sXg + (s & 1) * 2048;
#pragma unroll
        for (int r = 0; r < 2; r++) {
            int op = tid + (r << 8);
            int gb = op >> 1, half = op & 1;
            int gate = gb >> 6, b = gb & 63;
            cpa16(dst + gate * 512 + b * 8 + half * 4,
                  xgS + (size_t)b * G_ + (gate << 10) + u0 + half * 4);
        }
        cpa_commit();
    };

    prefetch_xg(0);
    __syncthreads();   // sWh visible to all warps

    for (int s = 0; s < S_; s++) {
        const float* hin = g_hbuf[s & 1];
        float* hout = g_hbuf[(s + 1) & 1];

        float acc[2][8][4];
#pragma unroll
        for (int mt = 0; mt < 2; mt++)
#pragma unroll
            for (int nt = 0; nt < 8; nt++)
#pragma unroll
                for (int j = 0; j < 4; j++) acc[mt][nt][j] = 0.f;

        if (s > 0) {
            auto stagec = [&](int t, int buf) {
                float* d = sStg + buf * STGB_F + w * 1280;
                const float* src = hin + w * 128 + t * 16;
#pragma unroll
                for (int r = 0; r < 8; r++) {
                    int op = lane + (r << 5);
                    int b = op >> 2, grp = op & 3;
                    cpa16(d + b * 20 + grp * 4, src + (size_t)b * H_ + grp * 4);
                }
                cpa_commit();
            };
            stagec(0, 0);
            for (int t = 0; t < 8; t++) {
                if (t < 7) { stagec(t + 1, (t + 1) & 1); cpa_wait<1>(); }
                else cpa_wait<0>();
                __syncwarp();
                const float* hb = sStg + (t & 1) * STGB_F + w * 1280;
#pragma unroll
                for (int kc = 0; kc < 2; kc++) {
                    int kb = w * 128 + t * 16 + kc * 8;
                    const float* R0 = sWh + ((kb + tg) << 5);
                    const float* R4 = sWh + ((kb + tg + 4) << 5);
                    int sw = tg << 3;
                    unsigned a0[4], a1[4];
                    a0[0] = __float_as_uint(R0[g + (0 ^ sw)]);
                    a0[1] = __float_as_uint(R0[g + (8 ^ sw)]);
                    a0[2] = __float_as_uint(R4[g + (0 ^ sw)]);
                    a0[3] = __float_as_uint(R4[g + (8 ^ sw)]);
                    a1[0] = __float_as_uint(R0[g + (16 ^ sw)]);
                    a1[1] = __float_as_uint(R0[g + (24 ^ sw)]);
                    a1[2] = __float_as_uint(R4[g + (16 ^ sw)]);
                    a1[3] = __float_as_uint(R4[g + (24 ^ sw)]);
#pragma unroll
                    for (int nt = 0; nt < 8; nt++) {
                        unsigned bb[2];
                        bb[0] = __float_as_uint(hb[(nt * 8 + g) * 20 + (kc << 3) + tg]);
                        bb[1] = __float_as_uint(hb[(nt * 8 + g) * 20 + (kc << 3) + tg + 4]);
                        mma_tf32(acc[0][nt], a0, bb);
                        mma_tf32(acc[1][nt], a1, bb);
                    }
                }
            }
        } else {
            cpa_wait<0>();
        }

        // prefetch next step's xg slice (independent of h)
        if (s + 1 < S_) prefetch_xg(s + 1);

        // ---- cross-warp reduce (rbuf aliases stage buffers) ----
        __syncthreads();   // all warps done reading stage buffers
        float* myr = rbuf + w * 2112 + lane * 66;
#pragma unroll
        for (int mt = 0; mt < 2; mt++)
#pragma unroll
            for (int nt = 0; nt < 8; nt++)
#pragma unroll
                for (int j = 0; j < 4; j++) myr[(mt * 8 + nt) * 4 + j] = acc[mt][nt][j];
        __syncthreads();
        float fin[2][4];
#pragma unroll
        for (int mt = 0; mt < 2; mt++)
#pragma unroll
            for (int j = 0; j < 4; j++) fin[mt][j] = 0.f;
#pragma unroll
        for (int src = 0; src < 8; src++) {
            const float* rr = rbuf + src * 2112 + lane * 66;
#pragma unroll
            for (int mt = 0; mt < 2; mt++)
#pragma unroll
                for (int j = 0; j < 4; j++) fin[mt][j] += rr[(mt * 8 + w) * 4 + j];
        }

        // ---- pointwise (state in registers) ----
        const float* xb = sXg + (s & 1) * 2048;
        int u = u0 + g;
#pragma unroll
        for (int hh = 0; hh < 2; hh++) {
            int bb = w * 8 + tg * 2 + hh;
            float iv = fin[0][hh]     + xb[bb * 8 + g];
            float fv = fin[0][2 + hh] + xb[512 + bb * 8 + g];
            float gv = fin[1][hh]     + xb[1024 + bb * 8 + g];
            float ov = fin[1][2 + hh] + xb[1536 + bb * 8 + g];
            float cn = sigm(fv) * creg[hh] + sigm(iv) * tanhf(gv);
            float hn = sigm(ov) * tanhf(cn);
            bool m = s < lenr[hh];
            float c  = m ? cn : creg[hh];
            float hf = m ? hn : hreg[hh];
            creg[hh] = c;
            hreg[hh] = hf;
            float hr = __uint_as_float(f2tf(hf));
            hout[bb * H_ + u] = hr;
            if (layer == 0) g_h1[((size_t)s * 64 + bb) * H_ + u] = hr;
            else            out[((size_t)bb * S_ + s) * H_ + u] = hf;
            if (s == S_ - 1) {
                out[OUT_CS + layer * LSTRIDE + bb * H_ + u] = c;
                out[OUT_HS + layer * LSTRIDE + bb * H_ + u] = hf;
            }
        }

        if (s < S_ - 1) grid_bar();
    }
}

// ---------------- launch ----------------
extern "C" void kernel_launch(void* const* d_in, const int* in_sizes, int n_in,
                              void* d_out, int out_size) {
    const int*   inputs  = (const int*)d_in[0];
    const int*   lengths = (const int*)d_in[1];
    const float* emb     = (const float*)d_in[3];
    const float* Wx      = (const float*)d_in[4];
    const float* Wh      = (const float*)d_in[5];
    const float* bias    = (const float*)d_in[6];
    float* out = (float*)d_out;

    cudaFuncSetAttribute(gemm_xg,   cudaFuncAttributeMaxDynamicSharedMemorySize, GEMM_SMEM);
    cudaFuncSetAttribute(lstm_pers, cudaFuncAttributeMaxDynamicSharedMemorySize, PS_SMEM);

    round_k<<<8192, 256>>>(Wx, 0);
    round_k<<<8192, 256>>>(Wh, 1);
    embed_kernel<<<NROW, 256>>>(inputs, emb);

    for (int l = 0; l < 2; l++) {
        gemm_xg<<<dim3(32, 128), 256, GEMM_SMEM>>>(l, bias + l * G_);
        lstm_pers<<<NCTA, 256, PS_SMEM>>>(l, lengths, out);
    }
}

// round 11
// speedup vs baseline: 1.9038x; 1.0551x over previous
#include <cuda_runtime.h>
#include <cstdint>
#include <math.h>

#define B_ 64
#define S_ 256
#define H_ 1024
#define G_ 4096
#define NROW (S_*B_)
#define NCTA 128

// ---------------- static scratch ----------------
__device__ float g_x  [NROW*H_];         // embedded, tf32-rounded [S,B,H]
__device__ float g_h1 [NROW*H_];         // layer-1 h seq, rounded [S,B,H]
__device__ float g_xg [(size_t)NROW*G_]; // gate preacts [S,B,4H]
__device__ float g_wxr[2*H_*G_];         // rounded Wx
__device__ float g_whr[2*H_*G_];         // rounded Wh
__device__ float g_hbuf[2][B_*H_];       // rounded h state, double buffered
__device__ unsigned g_flags[NCTA*32];    // barrier flags, 128B stride

// ---------------- helpers ----------------
__device__ __forceinline__ unsigned f2tf(float v) {
    unsigned r; asm("cvt.rna.tf32.f32 %0, %1;" : "=r"(r) : "f"(v)); return r;
}
__device__ __forceinline__ void mma_tf32(float* c, const unsigned* a, const unsigned* b) {
    asm volatile(
        "mma.sync.aligned.m16n8k8.row.col.f32.tf32.tf32.f32 "
        "{%0,%1,%2,%3}, {%4,%5,%6,%7}, {%8,%9}, {%0,%1,%2,%3};"
        : "+f"(c[0]), "+f"(c[1]), "+f"(c[2]), "+f"(c[3])
        : "r"(a[0]), "r"(a[1]), "r"(a[2]), "r"(a[3]), "r"(b[0]), "r"(b[1]));
}
__device__ __forceinline__ void cpa16(void* s, const void* g) {
    unsigned ss = (unsigned)__cvta_generic_to_shared(s);
    asm volatile("cp.async.cg.shared.global [%0], [%1], 16;" :: "r"(ss), "l"(g));
}
__device__ __forceinline__ void cpa_commit() { asm volatile("cp.async.commit_group;"); }
template<int N> __device__ __forceinline__ void cpa_wait() {
    asm volatile("cp.async.wait_group %0;" :: "n"(N));
}
__device__ __forceinline__ float sigm(float x) { return 1.f / (1.f + __expf(-x)); }

// distributed-flag grid barrier: no atomic contention.
__device__ __forceinline__ void flag_bar(unsigned target) {
    __syncthreads();
    if (threadIdx.x == 0) {
        asm volatile("st.release.gpu.global.u32 [%0], %1;"
                     :: "l"((unsigned*)&g_flags[blockIdx.x * 32]), "r"(target) : "memory");
    }
    if (threadIdx.x < NCTA) {
        const unsigned* p = (const unsigned*)&g_flags[threadIdx.x * 32];
        unsigned v;
        do {
            asm volatile("ld.acquire.gpu.global.u32 %0, [%1];" : "=r"(v) : "l"(p) : "memory");
        } while (v < target);
    }
    __syncthreads();
}

// ---------------- prep: round both weight tensors + reset barrier flags ------
__global__ void round_both(const float* __restrict__ wx, const float* __restrict__ wh) {
    if (blockIdx.x == 0 && threadIdx.x < NCTA) g_flags[threadIdx.x * 32] = 0;
    int half = blockIdx.x >> 13;                    // 0: Wx, 1: Wh
    size_t i = (size_t)(blockIdx.x & 8191) * 256 + threadIdx.x;  // float4 index
    const float* src = half ? wh : wx;
    float4 v = ((const float4*)src)[i];
    float4 o;
    o.x = __uint_as_float(f2tf(v.x)); o.y = __uint_as_float(f2tf(v.y));
    o.z = __uint_as_float(f2tf(v.z)); o.w = __uint_as_float(f2tf(v.w));
    ((float4*)(half ? g_whr : g_wxr))[i] = o;
}

// ---------------- embed ----------------
__global__ void embed_kernel(const int* __restrict__ inputs, const float* __restrict__ emb) {
    int rid = blockIdx.x;                  // s*64 + b
    int b = rid & 63, s = rid >> 6;
    int tok = inputs[b * S_ + s];
    float4 v = ((const float4*)(emb + (size_t)tok * H_))[threadIdx.x];
    float4 o;
    o.x = __uint_as_float(f2tf(v.x)); o.y = __uint_as_float(f2tf(v.y));
    o.z = __uint_as_float(f2tf(v.z)); o.w = __uint_as_float(f2tf(v.w));
    ((float4*)(g_x + (size_t)rid * H_))[threadIdx.x] = o;
}

// ---------------- xg GEMM: [16384,1024] @ [1024,4096] + bias ----------------
#define GBM 128
#define GBN 128
#define GBK 32
#define ALD 36
#define BLD 136
#define ABUF (GBM*ALD)
#define BBUF (GBK*BLD)
#define GEMM_SMEM ((2*(ABUF+BBUF))*4)

__global__ void __launch_bounds__(256, 2) gemm_xg(int layer, const float* __restrict__ bias) {
    extern __shared__ float sm[];
    float* As = sm;
    float* Bs = sm + 2 * ABUF;
    const float* A  = layer ? g_h1 : g_x;
    const float* Bw = g_wxr + (size_t)layer * H_ * G_;
    int tid = threadIdx.x;
    int bn = blockIdx.x, bm = blockIdx.y;
    const float* Ab = A + (size_t)bm * GBM * H_;
    const float* Bb = Bw + bn * GBN;
    int wid = tid >> 5, lane = tid & 31, g = lane >> 2, tg = lane & 3;
    int wm = (wid & 1) * 64, wn = (wid >> 1) * 32;

    float acc[4][4][4];
#pragma unroll
    for (int a = 0; a < 4; a++)
#pragma unroll
        for (int b = 0; b < 4; b++)
#pragma unroll
            for (int c = 0; c < 4; c++) acc[a][b][c] = 0.f;

    auto stage = [&](int it) {
        float* Ad = As + (it & 1) * ABUF;
        float* Bd = Bs + (it & 1) * BBUF;
        int k0 = it * GBK;
#pragma unroll
        for (int q = 0; q < 4; q++) {
            int idx = tid + q * 256; int r = idx >> 3, c4 = (idx & 7) << 2;
            cpa16(Ad + r * ALD + c4, Ab + (size_t)r * H_ + k0 + c4);
        }
#pragma unroll
        for (int q = 0; q < 4; q++) {
            int idx = tid + q * 256; int r = idx >> 5, c4 = (idx & 31) << 2;
            cpa16(Bd + r * BLD + c4, Bb + (size_t)(k0 + r) * G_ + c4);
        }
        cpa_commit();
    };

    stage(0);
    for (int it = 0; it < H_ / GBK; it++) {
        if (it + 1 < H_ / GBK) { stage(it + 1); cpa_wait<1>(); }
        else cpa_wait<0>();
        __syncthreads();
        const float* uA = As + (it & 1) * ABUF;
        const float* uB = Bs + (it & 1) * BBUF;
#pragma unroll
        for (int kk = 0; kk < 4; kk++) {
            unsigned af[4][4];
#pragma unroll
            for (int mt = 0; mt < 4; mt++) {
                int r0 = wm + mt * 16 + g; int k = kk * 8 + tg;
                af[mt][0] = __float_as_uint(uA[r0 * ALD + k]);
                af[mt][1] = __float_as_uint(uA[(r0 + 8) * ALD + k]);
                af[mt][2] = __float_as_uint(uA[r0 * ALD + k + 4]);
                af[mt][3] = __float_as_uint(uA[(r0 + 8) * ALD + k + 4]);
            }
            unsigned bf[4][2];
#pragma unroll
            for (int nt = 0; nt < 4; nt++) {
                int n = wn + nt * 8 + g;
                bf[nt][0] = __float_as_uint(uB[(kk * 8 + tg) * BLD + n]);
                bf[nt][1] = __float_as_uint(uB[(kk * 8 + tg + 4) * BLD + n]);
            }
#pragma unroll
            for (int mt = 0; mt < 4; mt++)
#pragma unroll
                for (int nt = 0; nt < 4; nt++) mma_tf32(acc[mt][nt], af[mt], bf[nt]);
        }
        __syncthreads();
    }

#pragma unroll
    for (int mt = 0; mt < 4; mt++)
#pragma unroll
        for (int nt = 0; nt < 4; nt++) {
            int row = bm * GBM + wm + mt * 16 + g;
            int col = bn * GBN + wn + nt * 8 + tg * 2;
            float b0 = bias[col], b1 = bias[col + 1];
            float* o = g_xg + (size_t)row * G_ + col;
            o[0] = acc[mt][nt][0] + b0; o[1] = acc[mt][nt][1] + b1;
            o = g_xg + (size_t)(row + 8) * G_ + col;
            o[0] = acc[mt][nt][2] + b0; o[1] = acc[mt][nt][3] + b1;
        }
}

// ---------------- persistent recurrent kernel ----------------
#define SWH_F 32768
#define STGB_F 10240
#define SXG_F 53248
#define PS_SMEM (57344*4)

#define OUT_CS 16777216
#define OUT_HS (16777216 + 2 * B_ * H_)
#define LSTRIDE (B_ * H_)

__global__ void __launch_bounds__(256) lstm_pers(int layer,
                                                 const int* __restrict__ lengths,
                                                 float* __restrict__ out) {
    extern __shared__ float sm[];
    float* sWh  = sm;
    float* sStg = sm + SWH_F;
    float* sXg  = sm + SXG_F;
    float* rbuf = sm + SWH_F;     // alias: used only after extra __syncthreads

    const float* whL = g_whr + (size_t)layer * H_ * G_;
    int tid = threadIdx.x, w = tid >> 5, lane = tid & 31, g = lane >> 2, tg = lane & 3;
    int u0 = blockIdx.x * 8;

    // ---- one-time: load CTA's Wh slice into swizzled smem ----
    for (int idx = tid; idx < 32768; idx += 256) {
        int k = idx >> 5, c = idx & 31;
        int gate = c >> 3, gg = c & 7;
        int cs = (((gate ^ (k & 3)) << 3) | gg);
        sWh[(k << 5) + cs] = whL[(size_t)k * G_ + (gate << 10) + u0 + gg];
    }

    float creg[2] = {0.f, 0.f}, hreg[2] = {0.f, 0.f};
    int lenr[2];
#pragma unroll
    for (int hh = 0; hh < 2; hh++) lenr[hh] = lengths[w * 8 + tg * 2 + hh];

    auto prefetch_xg = [&](int s) {
        const float* xgS = g_xg + (size_t)s * 64 * G_;
        float* dst = sXg + (s & 1) * 2048;
#pragma unroll
        for (int r = 0; r < 2; r++) {
            int op = tid + (r << 8);
            int gb = op >> 1, half = op & 1;
            int gate = gb >> 6, b = gb & 63;
            cpa16(dst + gate * 512 + b * 8 + half * 4,
                  xgS + (size_t)b * G_ + (gate << 10) + u0 + half * 4);
        }
        cpa_commit();
    };

    prefetch_xg(0);
    __syncthreads();   // sWh visible to all warps

    for (int s = 0; s < S_; s++) {
        const float* hin = g_hbuf[s & 1];
        float* hout = g_hbuf[(s + 1) & 1];

        float acc[2][8][4];
#pragma unroll
        for (int mt = 0; mt < 2; mt++)
#pragma unroll
            for (int nt = 0; nt < 8; nt++)
#pragma unroll
                for (int j = 0; j < 4; j++) acc[mt][nt][j] = 0.f;

        if (s > 0) {
            auto stagec = [&](int t, int buf) {
                float* d = sStg + buf * STGB_F + w * 1280;
                const float* src = hin + w * 128 + t * 16;
#pragma unroll
                for (int r = 0; r < 8; r++) {
                    int op = lane + (r << 5);
                    int b = op >> 2, grp = op & 3;
                    cpa16(d + b * 20 + grp * 4, src + (size_t)b * H_ + grp * 4);
                }
                cpa_commit();
            };
            stagec(0, 0);
            for (int t = 0; t < 8; t++) {
                if (t < 7) { stagec(t + 1, (t + 1) & 1); cpa_wait<1>(); }
                else cpa_wait<0>();
                __syncwarp();
                const float* hb = sStg + (t & 1) * STGB_F + w * 1280;
#pragma unroll
                for (int kc = 0; kc < 2; kc++) {
                    int kb = w * 128 + t * 16 + kc * 8;
                    const float* R0 = sWh + ((kb + tg) << 5);
                    const float* R4 = sWh + ((kb + tg + 4) << 5);
                    int sw = tg << 3;
                    unsigned a0[4], a1[4];
                    a0[0] = __float_as_uint(R0[g + (0 ^ sw)]);
                    a0[1] = __float_as_uint(R0[g + (8 ^ sw)]);
                    a0[2] = __float_as_uint(R4[g + (0 ^ sw)]);
                    a0[3] = __float_as_uint(R4[g + (8 ^ sw)]);
                    a1[0] = __float_as_uint(R0[g + (16 ^ sw)]);
                    a1[1] = __float_as_uint(R0[g + (24 ^ sw)]);
                    a1[2] = __float_as_uint(R4[g + (16 ^ sw)]);
                    a1[3] = __float_as_uint(R4[g + (24 ^ sw)]);
#pragma unroll
                    for (int nt = 0; nt < 8; nt++) {
                        unsigned bb[2];
                        bb[0] = __float_as_uint(hb[(nt * 8 + g) * 20 + (kc << 3) + tg]);
                        bb[1] = __float_as_uint(hb[(nt * 8 + g) * 20 + (kc << 3) + tg + 4]);
                        mma_tf32(acc[0][nt], a0, bb);
                        mma_tf32(acc[1][nt], a1, bb);
                    }
                }
            }
        } else {
            cpa_wait<0>();
        }

        // prefetch next step's xg slice (independent of h)
        if (s + 1 < S_) prefetch_xg(s + 1);

        // ---- cross-warp reduce (rbuf aliases stage buffers) ----
        __syncthreads();
        float* myr = rbuf + w * 2112 + lane * 66;
#pragma unroll
        for (int mt = 0; mt < 2; mt++)
#pragma unroll
            for (int nt = 0; nt < 8; nt++)
#pragma unroll
                for (int j = 0; j < 4; j++) myr[(mt * 8 + nt) * 4 + j] = acc[mt][nt][j];
        __syncthreads();
        float fin[2][4];
#pragma unroll
        for (int mt = 0; mt < 2; mt++)
#pragma unroll
            for (int j = 0; j < 4; j++) fin[mt][j] = 0.f;
#pragma unroll
        for (int src = 0; src < 8; src++) {
            const float* rr = rbuf + src * 2112 + lane * 66;
#pragma unroll
            for (int mt = 0; mt < 2; mt++)
#pragma unroll
                for (int j = 0; j < 4; j++) fin[mt][j] += rr[(mt * 8 + w) * 4 + j];
        }

        // ---- pointwise (state in registers) ----
        const float* xb = sXg + (s & 1) * 2048;
        int u = u0 + g;
#pragma unroll
        for (int hh = 0; hh < 2; hh++) {
            int bb = w * 8 + tg * 2 + hh;
            float iv = fin[0][hh]     + xb[bb * 8 + g];
            float fv = fin[0][2 + hh] + xb[512 + bb * 8 + g];
            float gv = fin[1][hh]     + xb[1024 + bb * 8 + g];
            float ov = fin[1][2 + hh] + xb[1536 + bb * 8 + g];
            float cn = sigm(fv) * creg[hh] + sigm(iv) * tanhf(gv);
            float hn = sigm(ov) * tanhf(cn);
            bool m = s < lenr[hh];
            float c  = m ? cn : creg[hh];
            float hf = m ? hn : hreg[hh];
            creg[hh] = c;
            hreg[hh] = hf;
            float hr = __uint_as_float(f2tf(hf));
            hout[bb * H_ + u] = hr;
            if (layer == 0) g_h1[((size_t)s * 64 + bb) * H_ + u] = hr;
            else            out[((size_t)bb * S_ + s) * H_ + u] = hf;
            if (s == S_ - 1) {
                out[OUT_CS + layer * LSTRIDE + bb * H_ + u] = c;
                out[OUT_HS + layer * LSTRIDE + bb * H_ + u] = hf;
            }
        }

        if (s < S_ - 1) flag_bar((unsigned)(layer * S_ + s + 1));
    }
}

// ---------------- launch ----------------
extern "C" void kernel_launch(void* const* d_in, const int* in_sizes, int n_in,
                              void* d_out, int out_size) {
    const int*   inputs  = (const int*)d_in[0];
    const int*   lengths = (const int*)d_in[1];
    const float* emb     = (const float*)d_in[3];
    const float* Wx      = (const float*)d_in[4];
    const float* Wh      = (const float*)d_in[5];
    const float* bias    = (const float*)d_in[6];
    float* out = (float*)d_out;

    cudaFuncSetAttribute(gemm_xg,   cudaFuncAttributeMaxDynamicSharedMemorySize, GEMM_SMEM);
    cudaFuncSetAttribute(lstm_pers, cudaFuncAttributeMaxDynamicSharedMemorySize, PS_SMEM);

    round_both<<<16384, 256>>>(Wx, Wh);
    embed_kernel<<<NROW, 256>>>(inputs, emb);

    for (int l = 0; l < 2; l++) {
        gemm_xg<<<dim3(32, 128), 256, GEMM_SMEM>>>(l, bias + l * G_);
        lstm_pers<<<NCTA, 256, PS_SMEM>>>(l, lengths, out);
    }
}